// round 8
// baseline (speedup 1.0000x reference)
#include <cuda_runtime.h>

#define T_DIM 3
#define B_DIM 100000
#define D_DIM 128
#define NEG_SLOPE 0.01f
#define TOTAL_ROWS (T_DIM * B_DIM)

// One warp per QUAD of consecutive (t,b) rows, one-shot grid. Each lane owns
// one float4 of each of the 4 rows. Per stream each warp covers 2KB contiguous
// (4 rows x 512B) with 24 outstanding loads -> maximal HBM burst locality.
// B_DIM % 4 == 0, so a quad never straddles a t boundary.
__global__ __launch_bounds__(256, 2)
void attconv_kernel(const float4* __restrict__ h_center,   // (T*B*32) float4
                    const float4* __restrict__ h_neigh,    // (T*T*B*32) float4
                    const float4* __restrict__ att_w,      // (T*64) float4
                    const float*  __restrict__ att_b,      // (T)
                    float4* __restrict__ out)              // (T*B*32) float4
{
    const int gwarp = (blockIdx.x * blockDim.x + threadIdx.x) >> 5;
    const int lane  = threadIdx.x & 31;
    const int row0  = gwarp * 4;                 // first row of the quad
    if (row0 >= TOTAL_ROWS) return;

    const int t  = row0 / B_DIM;                 // same t for all 4 rows
    const int b0 = row0 - t * B_DIM;

    const int ctr0 = row0 * 32 + lane;                         // center base
    const int nb0  = (t * T_DIM * B_DIM + b0) * 32 + lane;     // neigh base
    const int S    = B_DIM * 32;                               // neighbor stride

    // Weights (tiny, L2-resident after first wave).
    const float4 wh = __ldg(att_w + t * 64 + lane);
    const float4 we = __ldg(att_w + t * 64 + 32 + lane);
    const float bias = __ldg(att_b + t);

    // 16 big loads, all independent, issued up front.
    float4 c[4], v0[4], v1[4], v2[4];
    #pragma unroll
    for (int r = 0; r < 4; r++) c[r]  = __ldg(h_center + ctr0 + r * 32);
    #pragma unroll
    for (int r = 0; r < 4; r++) v0[r] = __ldg(h_neigh + nb0 + 0 * S + r * 32);
    #pragma unroll
    for (int r = 0; r < 4; r++) v1[r] = __ldg(h_neigh + nb0 + 1 * S + r * 32);
    #pragma unroll
    for (int r = 0; r < 4; r++) v2[r] = __ldg(h_neigh + nb0 + 2 * S + r * 32);

    // Partials per row, score_h folded in: sum(p_n + ph_lane) = P_n + PH.
    float p0[4], p1[4], p2[4], p3[4];
    #pragma unroll
    for (int r = 0; r < 4; r++) {
        float ph = c[r].x * wh.x + c[r].y * wh.y + c[r].z * wh.z + c[r].w * wh.w;
        p0[r] = v0[r].x * we.x + v0[r].y * we.y + v0[r].z * we.z + v0[r].w * we.w + ph;
        p1[r] = v1[r].x * we.x + v1[r].y * we.y + v1[r].z * we.z + v1[r].w * we.w + ph;
        p2[r] = v2[r].x * we.x + v2[r].y * we.y + v2[r].z * we.z + v2[r].w * we.w + ph;
        p3[r] = c[r].x  * we.x + c[r].y  * we.y + c[r].z  * we.z + c[r].w  * we.w + ph;
    }

    // 16 butterfly reductions, interleaved for ILP.
    #pragma unroll
    for (int off = 16; off > 0; off >>= 1) {
        #pragma unroll
        for (int r = 0; r < 4; r++) {
            p0[r] += __shfl_xor_sync(0xFFFFFFFFu, p0[r], off);
            p1[r] += __shfl_xor_sync(0xFFFFFFFFu, p1[r], off);
            p2[r] += __shfl_xor_sync(0xFFFFFFFFu, p2[r], off);
            p3[r] += __shfl_xor_sync(0xFFFFFFFFu, p3[r], off);
        }
    }

    // Softmax + weighted sum + store per row.
    #pragma unroll
    for (int r = 0; r < 4; r++) {
        float s0 = p0[r] + bias, s1 = p1[r] + bias;
        float s2 = p2[r] + bias, s3 = p3[r] + bias;
        s0 = (s0 >= 0.f) ? s0 : NEG_SLOPE * s0;
        s1 = (s1 >= 0.f) ? s1 : NEG_SLOPE * s1;
        s2 = (s2 >= 0.f) ? s2 : NEG_SLOPE * s2;
        s3 = (s3 >= 0.f) ? s3 : NEG_SLOPE * s3;
        float m = fmaxf(fmaxf(s0, s1), fmaxf(s2, s3));
        float e0 = __expf(s0 - m), e1 = __expf(s1 - m);
        float e2 = __expf(s2 - m), e3 = __expf(s3 - m);
        float inv = 1.0f / (e0 + e1 + e2 + e3);
        float w0 = e0 * inv, w1 = e1 * inv, w2 = e2 * inv, w3 = e3 * inv;
        float4 o;
        o.x = w0 * v0[r].x + w1 * v1[r].x + w2 * v2[r].x + w3 * c[r].x;
        o.y = w0 * v0[r].y + w1 * v1[r].y + w2 * v2[r].y + w3 * c[r].y;
        o.z = w0 * v0[r].z + w1 * v1[r].z + w2 * v2[r].z + w3 * c[r].z;
        o.w = w0 * v0[r].w + w1 * v1[r].w + w2 * v2[r].w + w3 * c[r].w;
        out[ctr0 + r * 32] = o;
    }
}

extern "C" void kernel_launch(void* const* d_in, const int* in_sizes, int n_in,
                              void* d_out, int out_size) {
    const float4* h_center = (const float4*)d_in[0];
    const float4* h_neigh  = (const float4*)d_in[1];
    const float4* att_w    = (const float4*)d_in[2];
    const float*  att_b    = (const float*)d_in[3];
    float4* out = (float4*)d_out;

    const int total_quads = TOTAL_ROWS / 4;             // 75000 warps
    const int threads = 256;                            // 8 warps/block
    const int blocks = (total_quads * 32 + threads - 1) / threads;  // 9375

    attconv_kernel<<<blocks, threads>>>(h_center, h_neigh, att_w, att_b, out);
}

// round 9
// speedup vs baseline: 1.0172x; 1.0172x over previous
#include <cuda_runtime.h>

#define T_DIM 3
#define B_DIM 100000
#define D_DIM 128
#define NEG_SLOPE 0.01f
#define TOTAL_ROWS (T_DIM * B_DIM)

// One warp per PAIR of consecutive (t,b) rows, one-shot grid (R7 config — the
// measured burst/occupancy sweet spot). Each lane owns one float4 of each row;
// 1KB contiguous per stream per warp, MLP=12. Streaming (.cs) hints on the
// zero-reuse tensors keep L2 from retaining dead lines.
__global__ __launch_bounds__(256, 4)
void attconv_kernel(const float4* __restrict__ h_center,   // (T*B*32) float4
                    const float4* __restrict__ h_neigh,    // (T*T*B*32) float4
                    const float4* __restrict__ att_w,      // (T*64) float4
                    const float*  __restrict__ att_b,      // (T)
                    float4* __restrict__ out)              // (T*B*32) float4
{
    const int gwarp = (blockIdx.x * blockDim.x + threadIdx.x) >> 5;
    const int lane  = threadIdx.x & 31;
    const int row0  = gwarp * 2;                 // first row of the pair
    if (row0 >= TOTAL_ROWS) return;

    const int t  = row0 / B_DIM;                 // same t for both rows
    const int b0 = row0 - t * B_DIM;

    const int ctr0 = row0 * 32 + lane;                         // row0 center
    const int nb0  = (t * T_DIM * B_DIM + b0) * 32 + lane;     // row0 neigh base

    // Issue all 12 big loads up front, streaming (zero reuse).
    const float4 ca = __ldcs(h_center + ctr0);
    const float4 cb = __ldcs(h_center + ctr0 + 32);
    const float4 a0 = __ldcs(h_neigh + nb0 + 0 * B_DIM * 32);
    const float4 b0v= __ldcs(h_neigh + nb0 + 0 * B_DIM * 32 + 32);
    const float4 a1 = __ldcs(h_neigh + nb0 + 1 * B_DIM * 32);
    const float4 b1v= __ldcs(h_neigh + nb0 + 1 * B_DIM * 32 + 32);
    const float4 a2 = __ldcs(h_neigh + nb0 + 2 * B_DIM * 32);
    const float4 b2v= __ldcs(h_neigh + nb0 + 2 * B_DIM * 32 + 32);
    const float4 wh = __ldg(att_w + t * 64 + lane);       // reused: keep cached
    const float4 we = __ldg(att_w + t * 64 + 32 + lane);
    const float bias = __ldg(att_b + t);

    // ---- row 0 partials (score_h folded in) ----
    float pha = ca.x * wh.x + ca.y * wh.y + ca.z * wh.z + ca.w * wh.w;
    float pa0 = a0.x * we.x + a0.y * we.y + a0.z * we.z + a0.w * we.w + pha;
    float pa1 = a1.x * we.x + a1.y * we.y + a1.z * we.z + a1.w * we.w + pha;
    float pa2 = a2.x * we.x + a2.y * we.y + a2.z * we.z + a2.w * we.w + pha;
    float pa3 = ca.x * we.x + ca.y * we.y + ca.z * we.z + ca.w * we.w + pha;
    // ---- row 1 partials ----
    float phb = cb.x * wh.x + cb.y * wh.y + cb.z * wh.z + cb.w * wh.w;
    float pb0 = b0v.x * we.x + b0v.y * we.y + b0v.z * we.z + b0v.w * we.w + phb;
    float pb1 = b1v.x * we.x + b1v.y * we.y + b1v.z * we.z + b1v.w * we.w + phb;
    float pb2 = b2v.x * we.x + b2v.y * we.y + b2v.z * we.z + b2v.w * we.w + phb;
    float pb3 = cb.x * we.x + cb.y * we.y + cb.z * we.z + cb.w * we.w + phb;

    // 8 butterfly reductions, interleaved for ILP.
    #pragma unroll
    for (int off = 16; off > 0; off >>= 1) {
        pa0 += __shfl_xor_sync(0xFFFFFFFFu, pa0, off);
        pa1 += __shfl_xor_sync(0xFFFFFFFFu, pa1, off);
        pa2 += __shfl_xor_sync(0xFFFFFFFFu, pa2, off);
        pa3 += __shfl_xor_sync(0xFFFFFFFFu, pa3, off);
        pb0 += __shfl_xor_sync(0xFFFFFFFFu, pb0, off);
        pb1 += __shfl_xor_sync(0xFFFFFFFFu, pb1, off);
        pb2 += __shfl_xor_sync(0xFFFFFFFFu, pb2, off);
        pb3 += __shfl_xor_sync(0xFFFFFFFFu, pb3, off);
    }

    // ---- row 0 softmax + output ----
    {
        float s0 = pa0 + bias, s1 = pa1 + bias, s2 = pa2 + bias, s3 = pa3 + bias;
        s0 = (s0 >= 0.f) ? s0 : NEG_SLOPE * s0;
        s1 = (s1 >= 0.f) ? s1 : NEG_SLOPE * s1;
        s2 = (s2 >= 0.f) ? s2 : NEG_SLOPE * s2;
        s3 = (s3 >= 0.f) ? s3 : NEG_SLOPE * s3;
        float m = fmaxf(fmaxf(s0, s1), fmaxf(s2, s3));
        float e0 = __expf(s0 - m), e1 = __expf(s1 - m);
        float e2 = __expf(s2 - m), e3 = __expf(s3 - m);
        float inv = 1.0f / (e0 + e1 + e2 + e3);
        float w0 = e0 * inv, w1 = e1 * inv, w2 = e2 * inv, w3 = e3 * inv;
        float4 o;
        o.x = w0 * a0.x + w1 * a1.x + w2 * a2.x + w3 * ca.x;
        o.y = w0 * a0.y + w1 * a1.y + w2 * a2.y + w3 * ca.y;
        o.z = w0 * a0.z + w1 * a1.z + w2 * a2.z + w3 * ca.z;
        o.w = w0 * a0.w + w1 * a1.w + w2 * a2.w + w3 * ca.w;
        __stcs(out + ctr0, o);
    }
    // ---- row 1 softmax + output ----
    {
        float s0 = pb0 + bias, s1 = pb1 + bias, s2 = pb2 + bias, s3 = pb3 + bias;
        s0 = (s0 >= 0.f) ? s0 : NEG_SLOPE * s0;
        s1 = (s1 >= 0.f) ? s1 : NEG_SLOPE * s1;
        s2 = (s2 >= 0.f) ? s2 : NEG_SLOPE * s2;
        s3 = (s3 >= 0.f) ? s3 : NEG_SLOPE * s3;
        float m = fmaxf(fmaxf(s0, s1), fmaxf(s2, s3));
        float e0 = __expf(s0 - m), e1 = __expf(s1 - m);
        float e2 = __expf(s2 - m), e3 = __expf(s3 - m);
        float inv = 1.0f / (e0 + e1 + e2 + e3);
        float w0 = e0 * inv, w1 = e1 * inv, w2 = e2 * inv, w3 = e3 * inv;
        float4 o;
        o.x = w0 * b0v.x + w1 * b1v.x + w2 * b2v.x + w3 * cb.x;
        o.y = w0 * b0v.y + w1 * b1v.y + w2 * b2v.y + w3 * cb.y;
        o.z = w0 * b0v.z + w1 * b1v.z + w2 * b2v.z + w3 * cb.z;
        o.w = w0 * b0v.w + w1 * b1v.w + w2 * b2v.w + w3 * cb.w;
        __stcs(out + ctr0 + 32, o);
    }
}

extern "C" void kernel_launch(void* const* d_in, const int* in_sizes, int n_in,
                              void* d_out, int out_size) {
    const float4* h_center = (const float4*)d_in[0];
    const float4* h_neigh  = (const float4*)d_in[1];
    const float4* att_w    = (const float4*)d_in[2];
    const float*  att_b    = (const float*)d_in[3];
    float4* out = (float4*)d_out;

    const int total_pairs = TOTAL_ROWS / 2;             // 150000 warps
    const int threads = 256;                            // 8 warps/block
    const int blocks = (total_pairs * 32 + threads - 1) / threads;  // 18750

    attconv_kernel<<<blocks, threads>>>(h_center, h_neigh, att_w, att_b, out);
}

// round 10
// speedup vs baseline: 1.0229x; 1.0056x over previous
#include <cuda_runtime.h>

#define T_DIM 3
#define B_DIM 100000
#define D_DIM 128
#define NEG_SLOPE 0.01f
#define TOTAL_ROWS (T_DIM * B_DIM)

// One warp per PAIR of consecutive (t,b) rows, one-shot grid. 512-thread CTAs
// (16 warps) double the per-CTA contiguous DRAM window per stream to 16KB for
// better row-buffer locality; same warps-per-SM as the 256-thread config.
// Streaming (.cs) on all zero-reuse tensors. Fast-approx softmax reciprocal
// (rel-err budget is 1e-3; we sit at 1e-7).
__global__ __launch_bounds__(512, 2)
void attconv_kernel(const float4* __restrict__ h_center,   // (T*B*32) float4
                    const float4* __restrict__ h_neigh,    // (T*T*B*32) float4
                    const float4* __restrict__ att_w,      // (T*64) float4
                    const float*  __restrict__ att_b,      // (T)
                    float4* __restrict__ out)              // (T*B*32) float4
{
    const int gwarp = (blockIdx.x * blockDim.x + threadIdx.x) >> 5;
    const int lane  = threadIdx.x & 31;
    const int row0  = gwarp * 2;                 // first row of the pair
    if (row0 >= TOTAL_ROWS) return;

    const int t  = row0 / B_DIM;                 // same t for both rows
    const int b0 = row0 - t * B_DIM;

    const int ctr0 = row0 * 32 + lane;                         // row0 center
    const int nb0  = (t * T_DIM * B_DIM + b0) * 32 + lane;     // row0 neigh base

    // Issue all 12 big loads up front, streaming (zero reuse).
    const float4 ca = __ldcs(h_center + ctr0);
    const float4 cb = __ldcs(h_center + ctr0 + 32);
    const float4 a0 = __ldcs(h_neigh + nb0 + 0 * B_DIM * 32);
    const float4 b0v= __ldcs(h_neigh + nb0 + 0 * B_DIM * 32 + 32);
    const float4 a1 = __ldcs(h_neigh + nb0 + 1 * B_DIM * 32);
    const float4 b1v= __ldcs(h_neigh + nb0 + 1 * B_DIM * 32 + 32);
    const float4 a2 = __ldcs(h_neigh + nb0 + 2 * B_DIM * 32);
    const float4 b2v= __ldcs(h_neigh + nb0 + 2 * B_DIM * 32 + 32);
    const float4 wh = __ldg(att_w + t * 64 + lane);       // reused: keep cached
    const float4 we = __ldg(att_w + t * 64 + 32 + lane);
    const float bias = __ldg(att_b + t);

    // ---- row 0 partials (score_h folded in) ----
    float pha = ca.x * wh.x + ca.y * wh.y + ca.z * wh.z + ca.w * wh.w;
    float pa0 = a0.x * we.x + a0.y * we.y + a0.z * we.z + a0.w * we.w + pha;
    float pa1 = a1.x * we.x + a1.y * we.y + a1.z * we.z + a1.w * we.w + pha;
    float pa2 = a2.x * we.x + a2.y * we.y + a2.z * we.z + a2.w * we.w + pha;
    float pa3 = ca.x * we.x + ca.y * we.y + ca.z * we.z + ca.w * we.w + pha;
    // ---- row 1 partials ----
    float phb = cb.x * wh.x + cb.y * wh.y + cb.z * wh.z + cb.w * wh.w;
    float pb0 = b0v.x * we.x + b0v.y * we.y + b0v.z * we.z + b0v.w * we.w + phb;
    float pb1 = b1v.x * we.x + b1v.y * we.y + b1v.z * we.z + b1v.w * we.w + phb;
    float pb2 = b2v.x * we.x + b2v.y * we.y + b2v.z * we.z + b2v.w * we.w + phb;
    float pb3 = cb.x * we.x + cb.y * we.y + cb.z * we.z + cb.w * we.w + phb;

    // 8 butterfly reductions, interleaved for ILP.
    #pragma unroll
    for (int off = 16; off > 0; off >>= 1) {
        pa0 += __shfl_xor_sync(0xFFFFFFFFu, pa0, off);
        pa1 += __shfl_xor_sync(0xFFFFFFFFu, pa1, off);
        pa2 += __shfl_xor_sync(0xFFFFFFFFu, pa2, off);
        pa3 += __shfl_xor_sync(0xFFFFFFFFu, pa3, off);
        pb0 += __shfl_xor_sync(0xFFFFFFFFu, pb0, off);
        pb1 += __shfl_xor_sync(0xFFFFFFFFu, pb1, off);
        pb2 += __shfl_xor_sync(0xFFFFFFFFu, pb2, off);
        pb3 += __shfl_xor_sync(0xFFFFFFFFu, pb3, off);
    }

    // ---- row 0 softmax + output ----
    {
        float s0 = pa0 + bias, s1 = pa1 + bias, s2 = pa2 + bias, s3 = pa3 + bias;
        s0 = (s0 >= 0.f) ? s0 : NEG_SLOPE * s0;
        s1 = (s1 >= 0.f) ? s1 : NEG_SLOPE * s1;
        s2 = (s2 >= 0.f) ? s2 : NEG_SLOPE * s2;
        s3 = (s3 >= 0.f) ? s3 : NEG_SLOPE * s3;
        float m = fmaxf(fmaxf(s0, s1), fmaxf(s2, s3));
        float e0 = __expf(s0 - m), e1 = __expf(s1 - m);
        float e2 = __expf(s2 - m), e3 = __expf(s3 - m);
        float inv = __fdividef(1.0f, e0 + e1 + e2 + e3);
        float w0 = e0 * inv, w1 = e1 * inv, w2 = e2 * inv, w3 = e3 * inv;
        float4 o;
        o.x = w0 * a0.x + w1 * a1.x + w2 * a2.x + w3 * ca.x;
        o.y = w0 * a0.y + w1 * a1.y + w2 * a2.y + w3 * ca.y;
        o.z = w0 * a0.z + w1 * a1.z + w2 * a2.z + w3 * ca.z;
        o.w = w0 * a0.w + w1 * a1.w + w2 * a2.w + w3 * ca.w;
        __stcs(out + ctr0, o);
    }
    // ---- row 1 softmax + output ----
    {
        float s0 = pb0 + bias, s1 = pb1 + bias, s2 = pb2 + bias, s3 = pb3 + bias;
        s0 = (s0 >= 0.f) ? s0 : NEG_SLOPE * s0;
        s1 = (s1 >= 0.f) ? s1 : NEG_SLOPE * s1;
        s2 = (s2 >= 0.f) ? s2 : NEG_SLOPE * s2;
        s3 = (s3 >= 0.f) ? s3 : NEG_SLOPE * s3;
        float m = fmaxf(fmaxf(s0, s1), fmaxf(s2, s3));
        float e0 = __expf(s0 - m), e1 = __expf(s1 - m);
        float e2 = __expf(s2 - m), e3 = __expf(s3 - m);
        float inv = __fdividef(1.0f, e0 + e1 + e2 + e3);
        float w0 = e0 * inv, w1 = e1 * inv, w2 = e2 * inv, w3 = e3 * inv;
        float4 o;
        o.x = w0 * b0v.x + w1 * b1v.x + w2 * b2v.x + w3 * cb.x;
        o.y = w0 * b0v.y + w1 * b1v.y + w2 * b2v.y + w3 * cb.y;
        o.z = w0 * b0v.z + w1 * b1v.z + w2 * b2v.z + w3 * cb.z;
        o.w = w0 * b0v.w + w1 * b1v.w + w2 * b2v.w + w3 * cb.w;
        __stcs(out + ctr0 + 32, o);
    }
}

extern "C" void kernel_launch(void* const* d_in, const int* in_sizes, int n_in,
                              void* d_out, int out_size) {
    const float4* h_center = (const float4*)d_in[0];
    const float4* h_neigh  = (const float4*)d_in[1];
    const float4* att_w    = (const float4*)d_in[2];
    const float*  att_b    = (const float*)d_in[3];
    float4* out = (float4*)d_out;

    const int total_pairs = TOTAL_ROWS / 2;             // 150000 warps
    const int threads = 512;                            // 16 warps/block
    const int blocks = (total_pairs * 32 + threads - 1) / threads;  // 9375

    attconv_kernel<<<blocks, threads>>>(h_center, h_neigh, att_w, att_b, out);
}